// round 7
// baseline (speedup 1.0000x reference)
#include <cuda_runtime.h>
#include <cstdint>
#include <math_constants.h>

// Sampler: penalties + temperature + top-k/top-p mask + gumbel sample + top-L logprobs.
// One CTA per row. Key insight: keep set is a prefix of the descending sort with
// length <= 63 (top_k in [32,64)), so only the top-64 values/indices per row are
// needed, plus the global max and full softmax denominator.
//
// Pass 1: read logits (DRAM), apply penalties on the fly, block-max + 11-bit
//         ordered-float histogram.
// Pass 2: re-read (L2-resident), accumulate sum(exp(x-M)), collect candidates
//         above histogram threshold bin into shared buffer.
// Epilogue: exact rank sort of candidates, prefix top-k/top-p, gumbel argmax
//         over <=63 gathered noise values, top-L logprob emission.

#define NT       1024
#define HB       2048          // histogram bins: top 11 bits of ordered float
#define CAND_CAP 1024
#define HASH_SZ  512
#define BM_WORDS 4096          // supports V up to 131072
#define BIG_NEG  (-1e30f)
#define SAMP_EPS 1e-5f

__device__ __forceinline__ unsigned ordf(float x) {
    unsigned u = __float_as_uint(x);
    return (u & 0x80000000u) ? ~u : (u | 0x80000000u);
}

__device__ __forceinline__ int hlookup(const int* hkey, const int* hcnt, int tok) {
    unsigned slot = ((unsigned)tok * 2654435761u) & (HASH_SZ - 1);
    while (true) {
        int k = hkey[slot];
        if (k == tok) return hcnt[slot];
        if (k == -1)  return 0;
        slot = (slot + 1) & (HASH_SZ - 1);
    }
}

__global__ __launch_bounds__(NT) void sampler_kernel(
    const float* __restrict__ logits,
    const int*   __restrict__ prompt_ids,
    const int*   __restrict__ output_ids,
    const int*   __restrict__ stop_ids,
    const int*   __restrict__ min_tokens,
    const float* __restrict__ presence,
    const float* __restrict__ frequency,
    const float* __restrict__ repetition,
    const float* __restrict__ temperature,
    const int*   __restrict__ top_k,
    const float* __restrict__ top_p,
    const float* __restrict__ noise,
    float*       __restrict__ out,
    int B, int V, int P, int O, int S, int L)
{
    __shared__ unsigned bm[BM_WORDS];      // prompt|output membership bitmap
    __shared__ int   hist[HB];
    __shared__ float candV[CAND_CAP];
    __shared__ int   candI[CAND_CAP];
    __shared__ int   hkey[HASH_SZ];        // output-token count hash
    __shared__ int   hcnt[HASH_SZ];
    __shared__ float sortedV[64];
    __shared__ int   sortedI[64];
    __shared__ float scoreV[64];
    __shared__ float redf[32];
    __shared__ int   shBstar, shCand, shNkept;
    __shared__ float shM, shS, shLse;

    const int b   = blockIdx.x;
    const int tid = threadIdx.x;

    // ---- init shared ----
    for (int i = tid; i < BM_WORDS; i += NT) bm[i] = 0u;
    for (int i = tid; i < HB;       i += NT) hist[i] = 0;
    for (int i = tid; i < HASH_SZ;  i += NT) { hkey[i] = -1; hcnt[i] = 0; }
    if (tid == 0) { shCand = 0; shBstar = 0; }
    __syncthreads();

    // ---- row params ----
    const bool  need = min_tokens[b] > O;
    const float rp = repetition[b], fp = frequency[b], pp = presence[b];
    const float traw = temperature[b];
    const float t = (traw < SAMP_EPS) ? 1.0f : traw;
    const int s0 = (S > 0) ? stop_ids[(size_t)b * S + 0] : -1;
    const int s1 = (S > 1) ? stop_ids[(size_t)b * S + 1] : -1;
    const int s2 = (S > 2) ? stop_ids[(size_t)b * S + 2] : -1;
    const int s3 = (S > 3) ? stop_ids[(size_t)b * S + 3] : -1;

    // ---- build membership bitmap + output counts ----
    for (int i = tid; i < O; i += NT) {
        int tok = output_ids[(size_t)b * O + i];
        atomicOr(&bm[tok >> 5], 1u << (tok & 31));
        unsigned slot = ((unsigned)tok * 2654435761u) & (HASH_SZ - 1);
        while (true) {
            int old = atomicCAS(&hkey[slot], -1, tok);
            if (old == -1 || old == tok) { atomicAdd(&hcnt[slot], 1); break; }
            slot = (slot + 1) & (HASH_SZ - 1);
        }
    }
    for (int i = tid; i < P; i += NT) {
        int tok = prompt_ids[(size_t)b * P + i];
        atomicOr(&bm[tok >> 5], 1u << (tok & 31));
    }
    __syncthreads();

    const float* lrow = logits + (size_t)b * V;

    // ================= PASS 1: max + histogram =================
    float m = -CUDART_INF_F;
    for (int base = tid * 4; base < V; base += NT * 4) {
        float4 q = *reinterpret_cast<const float4*>(lrow + base);
        float xs[4] = {q.x, q.y, q.z, q.w};
        unsigned w = bm[base >> 5];
        #pragma unroll
        for (int j = 0; j < 4; j++) {
            int v = base + j;
            float x = xs[j];
            if (need && (v == s0 || v == s1 || v == s2 || v == s3))
                x = fminf(x, BIG_NEG);
            if ((w >> (v & 31)) & 1u) {
                x = (x > 0.0f) ? (x / rp) : (x * rp);
                int c = hlookup(hkey, hcnt, v);
                if (c > 0) x -= fp * (float)c + pp;
            }
            x = x / t;
            m = fmaxf(m, x);
            atomicAdd(&hist[ordf(x) >> 21], 1);
        }
    }
    // block max -> shM
    for (int o = 16; o; o >>= 1) m = fmaxf(m, __shfl_xor_sync(0xffffffffu, m, o));
    if ((tid & 31) == 0) redf[tid >> 5] = m;
    __syncthreads();
    if (tid < 32) {
        float v = redf[tid];
        for (int o = 16; o; o >>= 1) v = fmaxf(v, __shfl_xor_sync(0xffffffffu, v, o));
        if (tid == 0) shM = v;
    }
    __syncthreads();

    // ---- threshold bin: highest bin where cumulative-from-top >= 64 ----
    // (total mass = V >= 64, so the crossing always exists; shBstar is
    //  guaranteed to be written exactly once.)
    if (tid < 32) {
        int running = 0;
        for (int base = HB - 1; base >= 0; base -= 32) {
            int bin = base - (int)tid;              // lane 0 = highest bin
            int cnt = (bin >= 0) ? hist[bin] : 0;
            int pref = cnt;                          // inclusive prefix (descending bins)
            for (int o = 1; o < 32; o <<= 1) {
                int nv = __shfl_up_sync(0xffffffffu, pref, o);
                if ((int)tid >= o) pref += nv;
            }
            int tot = __shfl_sync(0xffffffffu, pref, 31);
            if (running + tot >= 64) {
                unsigned msk = __ballot_sync(0xffffffffu, running + pref >= 64);
                int Lm = __ffs(msk) - 1;
                int bstar = base - Lm;
                if (bstar < 0) bstar = 0;
                if (tid == 0) shBstar = bstar;
                break;
            }
            running += tot;
        }
    }
    __syncthreads();

    // ================= PASS 2: sum(exp) + candidates =================
    const float M = shM;
    const int bstar = shBstar;
    float s = 0.0f;
    for (int base = tid * 4; base < V; base += NT * 4) {
        float4 q = *reinterpret_cast<const float4*>(lrow + base);
        float xs[4] = {q.x, q.y, q.z, q.w};
        unsigned w = bm[base >> 5];
        #pragma unroll
        for (int j = 0; j < 4; j++) {
            int v = base + j;
            float x = xs[j];
            if (need && (v == s0 || v == s1 || v == s2 || v == s3))
                x = fminf(x, BIG_NEG);
            if ((w >> (v & 31)) & 1u) {
                x = (x > 0.0f) ? (x / rp) : (x * rp);
                int c = hlookup(hkey, hcnt, v);
                if (c > 0) x -= fp * (float)c + pp;
            }
            x = x / t;
            s += expf(x - M);
            if ((int)(ordf(x) >> 21) >= bstar) {
                int p = atomicAdd(&shCand, 1);
                if (p < CAND_CAP) { candV[p] = x; candI[p] = v; }
            }
        }
    }
    // block sum -> shS
    for (int o = 16; o; o >>= 1) s += __shfl_xor_sync(0xffffffffu, s, o);
    if ((tid & 31) == 0) redf[tid >> 5] = s;
    __syncthreads();
    if (tid < 32) {
        float v = redf[tid];
        for (int o = 16; o; o >>= 1) v += __shfl_xor_sync(0xffffffffu, v, o);
        if (tid == 0) shS = v;
    }
    __syncthreads();

    // ---- exact rank sort of candidates (value desc, index asc; stable) ----
    const int C = min(shCand, CAND_CAP);
    const int Ntop = min(64, C);
    for (int i = tid; i < C; i += NT) {
        float vi = candV[i]; int ii = candI[i];
        int r = 0;
        for (int j = 0; j < C; j++) {
            float vj = candV[j];
            if (vj > vi || (vj == vi && candI[j] < ii)) r++;
        }
        if (r < 64) { sortedV[r] = vi; sortedI[r] = ii; }
    }
    __syncthreads();

    // ---- prefix top-k & top-p (exclusive cumsum, strict <), masked LSE ----
    if (tid == 0) {
        const float Sall = shS;
        int ke = top_k[b]; if (ke < 1) ke = V;
        const float tp = top_p[b];
        float c = 0.0f; int nk = 0;
        for (int i = 0; i < Ntop; i++) {
            if (i < ke && c < tp) { nk = i + 1; c += expf(sortedV[i] - M) / Sall; }
            else break;
        }
        float sum = 0.0f;
        for (int i = 0; i < nk; i++) sum += expf(sortedV[i] - M);
        shLse = M + logf(sum);
        shNkept = nk;
    }
    __syncthreads();
    const int nk = shNkept;
    const float lse = shLse;

    // ---- gumbel scores over kept set (parallel noise gather) ----
    if (tid < nk) {
        int idx = sortedI[tid];
        float u = noise[(size_t)b * V + idx];
        float g = -logf(-logf(u));
        scoreV[tid] = sortedV[tid] / t + g;
    }
    __syncthreads();
    if (tid == 0) {
        int best;
        if (traw < SAMP_EPS) {
            best = sortedI[0];                       // greedy: ties -> lowest index
        } else {
            best = sortedI[0]; float bs = scoreV[0];
            for (int i = 1; i < nk; i++) {
                float sc = scoreV[i]; int ix = sortedI[i];
                if (sc > bs || (sc == bs && ix < best)) { bs = sc; best = ix; }
            }
        }
        out[b] = (float)best;
    }

    // ---- top-L logprobs + indices ----
    float* lpOut = out + B + (size_t)b * L;
    float* ixOut = out + B + (size_t)B * L + (size_t)b * L;
    if (tid < L) {
        if (tid < nk) {
            lpOut[tid] = sortedV[tid] - lse;
            ixOut[tid] = (float)sortedI[tid];
        } else {
            lpOut[tid] = BIG_NEG;                    // exact: -1e30 - lse == -1e30 in f32
        }
    }
    // fill remaining index slots with the smallest non-kept token ids
    // (lax.top_k tie-break: ascending index among equal BIG_NEG values)
    const int needFill = L - nk;
    if (needFill > 0 && tid < 192) {
        int cid = tid;
        bool inKept = false; int less = 0;
        for (int i = 0; i < nk; i++) {
            int si = sortedI[i];
            inKept |= (si == cid);
            less += (si < cid);
        }
        if (!inKept) {
            int rank = cid - less;                   // rank among non-kept ids
            if (rank < needFill) ixOut[nk + rank] = (float)cid;
        }
    }
}

extern "C" void kernel_launch(void* const* d_in, const int* in_sizes, int n_in,
                              void* d_out, int out_size) {
    const float* logits  = (const float*)d_in[0];
    const int*   prompt  = (const int*)  d_in[1];
    const int*   outtok  = (const int*)  d_in[2];
    const int*   stoptok = (const int*)  d_in[3];
    const int*   mintok  = (const int*)  d_in[4];
    const float* pres    = (const float*)d_in[5];
    const float* freq    = (const float*)d_in[6];
    const float* rep     = (const float*)d_in[7];
    const float* temp    = (const float*)d_in[8];
    const int*   topk    = (const int*)  d_in[9];
    const float* topp    = (const float*)d_in[10];
    const float* noise   = (const float*)d_in[11];

    const int B = in_sizes[4];
    const int V = in_sizes[0] / B;
    const int P = in_sizes[1] / B;
    const int O = in_sizes[2] / B;
    const int S = in_sizes[3] / B;
    const int L = (out_size / B - 1) / 2;   // [sampled(B), logprobs(B,L), indices(B,L)]

    sampler_kernel<<<B, NT>>>(logits, prompt, outtok, stoptok, mintok,
                              pres, freq, rep, temp, topk, topp, noise,
                              (float*)d_out, B, V, P, O, S, L);
}

// round 8
// speedup vs baseline: 1.3889x; 1.3889x over previous
#include <cuda_runtime.h>
#include <cstdint>
#include <math_constants.h>

// Sampler: penalties + temperature + top-k/top-p mask + gumbel sample + top-L logprobs.
// One CTA per row.
//
// Keep set is a prefix of the descending sort with length <= 63 (top_k in [32,64)),
// so only the top-64 (value,index) pairs per row are needed, plus the global max
// and the full softmax denominator.
//
// R8 change vs R7: the per-element shared-atomic histogram (1 ATOMS per element,
// ~2cyc/lane => ~256K cyc/SM, ~95% of runtime) is replaced by an exact
// order-statistics bound: the 64th-largest of the 1024 per-thread maxima is
// always <= the 64th-largest element. Pass 1 is now a pure fmax scan; only the
// 1024 thread-maxes get histogrammed (1024 atomics total per row).

#define NT       1024
#define SHIFT    20
#define HB       4096          // ordered-float bins: ordf(x) >> 20
#define CAND_CAP 2048
#define HASH_SZ  512
#define BM_WORDS 4096          // supports V up to 131072
#define BIG_NEG  (-1e30f)
#define SAMP_EPS 1e-5f

__device__ __forceinline__ unsigned ordf(float x) {
    unsigned u = __float_as_uint(x);
    return (u & 0x80000000u) ? ~u : (u | 0x80000000u);
}

__device__ __forceinline__ int hlookup(const int* hkey, const int* hcnt, int tok) {
    unsigned slot = ((unsigned)tok * 2654435761u) & (HASH_SZ - 1);
    while (true) {
        int k = hkey[slot];
        if (k == tok) return hcnt[slot];
        if (k == -1)  return 0;
        slot = (slot + 1) & (HASH_SZ - 1);
    }
}

// penalized, temperature-scaled logit
template<bool NEED>
__device__ __forceinline__ float xform(float x, int v, unsigned w,
    int s0, int s1, int s2, int s3,
    float rp, float fp, float pp, float invt,
    const int* hkey, const int* hcnt)
{
    if (NEED && (v == s0 || v == s1 || v == s2 || v == s3))
        x = fminf(x, BIG_NEG);
    if ((w >> (v & 31)) & 1u) {
        x = (x > 0.0f) ? (x / rp) : (x * rp);
        int c = hlookup(hkey, hcnt, v);
        if (c > 0) x -= fp * (float)c + pp;
    }
    return x * invt;
}

template<bool NEED>
__device__ __forceinline__ float pass1_max(const float* lrow, int V, int tid,
    const unsigned* bm, const int* hkey, const int* hcnt,
    int s0, int s1, int s2, int s3,
    float rp, float fp, float pp, float invt)
{
    float m = -CUDART_INF_F;
    for (int base = tid * 4; base < V; base += NT * 4) {
        float4 q = *reinterpret_cast<const float4*>(lrow + base);
        unsigned w = bm[base >> 5];
        float xs[4] = {q.x, q.y, q.z, q.w};
        #pragma unroll
        for (int j = 0; j < 4; j++) {
            float x = xform<NEED>(xs[j], base + j, w, s0, s1, s2, s3,
                                  rp, fp, pp, invt, hkey, hcnt);
            m = fmaxf(m, x);
        }
    }
    return m;
}

template<bool NEED>
__device__ __forceinline__ float pass2_scan(const float* lrow, int V, int tid,
    const unsigned* bm, const int* hkey, const int* hcnt,
    int s0, int s1, int s2, int s3,
    float rp, float fp, float pp, float invt,
    float M, float theta,
    float* candV, int* candI, int* shCand)
{
    float s = 0.0f;
    for (int base = tid * 4; base < V; base += NT * 4) {
        float4 q = *reinterpret_cast<const float4*>(lrow + base);
        unsigned w = bm[base >> 5];
        float xs[4] = {q.x, q.y, q.z, q.w};
        #pragma unroll
        for (int j = 0; j < 4; j++) {
            float x = xform<NEED>(xs[j], base + j, w, s0, s1, s2, s3,
                                  rp, fp, pp, invt, hkey, hcnt);
            s += __expf(x - M);
            if (x >= theta) {
                int p = atomicAdd(shCand, 1);
                if (p < CAND_CAP) { candV[p] = x; candI[p] = base + j; }
            }
        }
    }
    return s;
}

__global__ __launch_bounds__(NT) void sampler_kernel(
    const float* __restrict__ logits,
    const int*   __restrict__ prompt_ids,
    const int*   __restrict__ output_ids,
    const int*   __restrict__ stop_ids,
    const int*   __restrict__ min_tokens,
    const float* __restrict__ presence,
    const float* __restrict__ frequency,
    const float* __restrict__ repetition,
    const float* __restrict__ temperature,
    const int*   __restrict__ top_k,
    const float* __restrict__ top_p,
    const float* __restrict__ noise,
    float*       __restrict__ out,
    int B, int V, int P, int O, int S, int L)
{
    __shared__ unsigned bm[BM_WORDS];          // 16KB membership bitmap
    __shared__ int   hkey[HASH_SZ];            // output-token count hash (4KB)
    __shared__ int   hcnt[HASH_SZ];
    __shared__ int   scratch[HB + NT];         // 20KB, phase-overlaid:
    // phase 1: hist = scratch[0..HB), tmax = scratch[HB..HB+NT)
    // phase 2: candV = scratch[0..CAND_CAP), candI = scratch[CAND_CAP..2*CAND_CAP)
    int*   hist  = scratch;
    float* tmax  = reinterpret_cast<float*>(scratch + HB);
    float* candV = reinterpret_cast<float*>(scratch);
    int*   candI = scratch + CAND_CAP;

    __shared__ float sortedV[64];
    __shared__ int   sortedI[64];
    __shared__ float scoreV[64];
    __shared__ float redf[32];
    __shared__ int   shCand, shNkept;
    __shared__ float shM, shS, shLse, shTheta;

    const int b   = blockIdx.x;
    const int tid = threadIdx.x;

    // ---- init shared ----
    for (int i = tid; i < BM_WORDS; i += NT) bm[i] = 0u;
    for (int i = tid; i < HB;       i += NT) hist[i] = 0;
    for (int i = tid; i < HASH_SZ;  i += NT) { hkey[i] = -1; hcnt[i] = 0; }
    if (tid == 0) shCand = 0;
    __syncthreads();

    // ---- row params ----
    const bool  need = min_tokens[b] > O;
    const float rp = repetition[b], fp = frequency[b], pp = presence[b];
    const float traw = temperature[b];
    const float t = (traw < SAMP_EPS) ? 1.0f : traw;
    const float invt = 1.0f / t;
    const int s0 = (S > 0) ? stop_ids[(size_t)b * S + 0] : -1;
    const int s1 = (S > 1) ? stop_ids[(size_t)b * S + 1] : -1;
    const int s2 = (S > 2) ? stop_ids[(size_t)b * S + 2] : -1;
    const int s3 = (S > 3) ? stop_ids[(size_t)b * S + 3] : -1;

    // ---- build membership bitmap + output counts ----
    for (int i = tid; i < O; i += NT) {
        int tok = output_ids[(size_t)b * O + i];
        atomicOr(&bm[tok >> 5], 1u << (tok & 31));
        unsigned slot = ((unsigned)tok * 2654435761u) & (HASH_SZ - 1);
        while (true) {
            int old = atomicCAS(&hkey[slot], -1, tok);
            if (old == -1 || old == tok) { atomicAdd(&hcnt[slot], 1); break; }
            slot = (slot + 1) & (HASH_SZ - 1);
        }
    }
    for (int i = tid; i < P; i += NT) {
        int tok = prompt_ids[(size_t)b * P + i];
        atomicOr(&bm[tok >> 5], 1u << (tok & 31));
    }
    __syncthreads();

    const float* lrow = logits + (size_t)b * V;

    // ================= PASS 1: per-thread max (no atomics) =================
    float m = need
        ? pass1_max<true >(lrow, V, tid, bm, hkey, hcnt, s0, s1, s2, s3, rp, fp, pp, invt)
        : pass1_max<false>(lrow, V, tid, bm, hkey, hcnt, s0, s1, s2, s3, rp, fp, pp, invt);
    tmax[tid] = m;
    // histogram of the 1024 thread-maxes only
    atomicAdd(&hist[ordf(m) >> SHIFT], 1);
    __syncthreads();

    // ---- block max M (reduce over tmax) ----
    if (tid < 32) {
        float v = -CUDART_INF_F;
        for (int i = tid; i < NT; i += 32) v = fmaxf(v, tmax[i]);
        for (int o = 16; o; o >>= 1) v = fmaxf(v, __shfl_xor_sync(0xffffffffu, v, o));
        if (tid == 0) shM = v;
    }

    // ---- threshold: highest bin where cumulative-from-top >= 64 ----
    // (total mass = NT = 1024 >= 64, so the crossing always exists)
    if (tid >= 32 && tid < 64) {
        const int lt = tid - 32;
        int running = 0;
        for (int base = HB - 1; base >= 0; base -= 32) {
            int bin = base - lt;                    // lane 0 = highest bin
            int cnt = (bin >= 0) ? hist[bin] : 0;
            int pref = cnt;                          // inclusive prefix (descending bins)
            for (int o = 1; o < 32; o <<= 1) {
                int nv = __shfl_up_sync(0xffffffffu, pref, o);
                if (lt >= o) pref += nv;
            }
            int tot = __shfl_sync(0xffffffffu, pref, 31);
            if (running + tot >= 64) {
                unsigned msk = __ballot_sync(0xffffffffu, running + pref >= 64);
                int Lm = __ffs(msk) - 1;
                int bstar = base - Lm;
                if (bstar < 0) bstar = 0;
                if (lt == 0) {
                    // decode bin lower edge (ordered -> float); guaranteed <= x64
                    unsigned tu = (unsigned)bstar << SHIFT;
                    float th;
                    if (tu == 0u)               th = -CUDART_INF_F;
                    else if (tu & 0x80000000u)  th = __uint_as_float(tu ^ 0x80000000u);
                    else                        th = __uint_as_float(~tu);
                    shTheta = th;
                }
                break;
            }
            running += tot;
        }
    }
    __syncthreads();

    // ================= PASS 2: sum(exp) + candidates (L2-resident) =================
    const float M = shM;
    const float theta = shTheta;
    float s = need
        ? pass2_scan<true >(lrow, V, tid, bm, hkey, hcnt, s0, s1, s2, s3,
                            rp, fp, pp, invt, M, theta, candV, candI, &shCand)
        : pass2_scan<false>(lrow, V, tid, bm, hkey, hcnt, s0, s1, s2, s3,
                            rp, fp, pp, invt, M, theta, candV, candI, &shCand);
    // block sum -> shS (fixed reduction order: deterministic)
    for (int o = 16; o; o >>= 1) s += __shfl_xor_sync(0xffffffffu, s, o);
    if ((tid & 31) == 0) redf[tid >> 5] = s;
    __syncthreads();
    if (tid < 32) {
        float v = redf[tid];
        for (int o = 16; o; o >>= 1) v += __shfl_xor_sync(0xffffffffu, v, o);
        if (tid == 0) shS = v;
    }
    __syncthreads();

    // ---- exact rank sort of candidates (value desc, index asc; stable) ----
    const int C = min(shCand, CAND_CAP);
    const int Ntop = min(64, C);
    for (int i = tid; i < C; i += NT) {
        float vi = candV[i]; int ii = candI[i];
        int r = 0;
        for (int j = 0; j < C; j++) {
            float vj = candV[j];
            if (vj > vi || (vj == vi && candI[j] < ii)) r++;
        }
        if (r < 64) { sortedV[r] = vi; sortedI[r] = ii; }
    }
    __syncthreads();

    // ---- prefix top-k & top-p (exclusive cumsum, strict <), masked LSE ----
    if (tid == 0) {
        const float Sall = shS;
        int ke = top_k[b]; if (ke < 1) ke = V;
        const float tp = top_p[b];
        float c = 0.0f; int nk = 0;
        for (int i = 0; i < Ntop; i++) {
            if (i < ke && c < tp) { nk = i + 1; c += expf(sortedV[i] - M) / Sall; }
            else break;
        }
        float sum = 0.0f;
        for (int i = 0; i < nk; i++) sum += expf(sortedV[i] - M);
        shLse = M + logf(sum);
        shNkept = nk;
    }
    __syncthreads();
    const int nk = shNkept;
    const float lse = shLse;

    // ---- gumbel scores over kept set (parallel noise gather) ----
    if (tid < nk) {
        int idx = sortedI[tid];
        float u = noise[(size_t)b * V + idx];
        float g = -logf(-logf(u));
        scoreV[tid] = sortedV[tid] * invt + g;
    }
    __syncthreads();
    if (tid == 0) {
        int best;
        if (traw < SAMP_EPS) {
            best = sortedI[0];                       // greedy: ties -> lowest index
        } else {
            best = sortedI[0]; float bs = scoreV[0];
            for (int i = 1; i < nk; i++) {
                float sc = scoreV[i]; int ix = sortedI[i];
                if (sc > bs || (sc == bs && ix < best)) { bs = sc; best = ix; }
            }
        }
        out[b] = (float)best;
    }

    // ---- top-L logprobs + indices ----
    float* lpOut = out + B + (size_t)b * L;
    float* ixOut = out + B + (size_t)B * L + (size_t)b * L;
    if (tid < L) {
        if (tid < nk) {
            lpOut[tid] = sortedV[tid] - lse;
            ixOut[tid] = (float)sortedI[tid];
        } else {
            lpOut[tid] = BIG_NEG;                    // exact: -1e30 - lse == -1e30 in f32
        }
    }
    // fill remaining index slots with the smallest non-kept token ids
    // (lax.top_k tie-break: ascending index among equal BIG_NEG values)
    const int needFill = L - nk;
    if (needFill > 0 && tid < 192) {
        int cid = tid;
        bool inKept = false; int less = 0;
        for (int i = 0; i < nk; i++) {
            int si = sortedI[i];
            inKept |= (si == cid);
            less += (si < cid);
        }
        if (!inKept) {
            int rank = cid - less;                   // rank among non-kept ids
            if (rank < needFill) ixOut[nk + rank] = (float)cid;
        }
    }
}

extern "C" void kernel_launch(void* const* d_in, const int* in_sizes, int n_in,
                              void* d_out, int out_size) {
    const float* logits  = (const float*)d_in[0];
    const int*   prompt  = (const int*)  d_in[1];
    const int*   outtok  = (const int*)  d_in[2];
    const int*   stoptok = (const int*)  d_in[3];
    const int*   mintok  = (const int*)  d_in[4];
    const float* pres    = (const float*)d_in[5];
    const float* freq    = (const float*)d_in[6];
    const float* rep     = (const float*)d_in[7];
    const float* temp    = (const float*)d_in[8];
    const int*   topk    = (const int*)  d_in[9];
    const float* topp    = (const float*)d_in[10];
    const float* noise   = (const float*)d_in[11];

    const int B = in_sizes[4];
    const int V = in_sizes[0] / B;
    const int P = in_sizes[1] / B;
    const int O = in_sizes[2] / B;
    const int S = in_sizes[3] / B;
    const int L = (out_size / B - 1) / 2;   // [sampled(B), logprobs(B,L), indices(B,L)]

    sampler_kernel<<<B, NT>>>(logits, prompt, outtok, stoptok, mintok,
                              pres, freq, rep, temp, topk, topp, noise,
                              (float*)d_out, B, V, P, O, S, L);
}

// round 9
// speedup vs baseline: 1.9255x; 1.3864x over previous
#include <cuda_runtime.h>
#include <cstdint>
#include <math_constants.h>

// Sampler: penalties + temperature + top-k/top-p mask + gumbel sample + top-L logprobs.
// One CTA per row.
//
// R9 change vs R8: penalty/stop/hash work is removed from the two V-wide scans
// (measured ~49 instr/elem due to warp divergence into the FDIV + hash-probe
// path on ~90% of warp iterations). Masked tokens (<= P+O+4 ~ 2308 distinct,
// recorded in the shared bitmap) are handled by a sparse phase that walks the
// bitmap. Main loops: pass1 = raw fmax (~4 instr/elem), pass2 = exp-sum +
// candidate filter (~8 instr/elem). Exactness of the top-64 candidate bound is
// preserved: each thread's max covers its main tokens (masked -> -inf) plus its
// bitmap-word share of special tokens; union covers all V, so at most 63
// thread-maxes exceed x64 and the 64th-largest thread-max <= x64.

#define NT       1024
#define SHIFT    20
#define HB       4096          // ordered-float bins: ordf(x) >> 20
#define CAND_CAP 2048
#define HASH_SZ  512
#define BM_WORDS 4096          // supports V up to 131072
#define WPT      (BM_WORDS / NT)
#define BIG_NEG  (-1e30f)
#define SAMP_EPS 1e-5f

__device__ __forceinline__ unsigned ordf(float x) {
    unsigned u = __float_as_uint(x);
    return (u & 0x80000000u) ? ~u : (u | 0x80000000u);
}

__device__ __forceinline__ int hlookup(const int* hkey, const int* hcnt, int tok) {
    unsigned slot = ((unsigned)tok * 2654435761u) & (HASH_SZ - 1);
    while (true) {
        int k = hkey[slot];
        if (k == tok) return hcnt[slot];
        if (k == -1)  return 0;
        slot = (slot + 1) & (HASH_SZ - 1);
    }
}

// Full reference-order transform for a special (bitmap-marked) token:
// stop-min (if needed) -> repetition (if prompt/output member) -> freq/presence
// (if output member) -> temperature.
__device__ __forceinline__ float spec_val(float x, int v, bool need,
    int s0, int s1, int s2, int s3, const int* stopPenSh,
    float rp, float fp, float pp, float invt,
    const int* hkey, const int* hcnt)
{
    bool penal = true;
    if (need) {
        int which = (v == s0) ? 0 : (v == s1) ? 1 : (v == s2) ? 2 : (v == s3) ? 3 : -1;
        if (which >= 0) {
            penal = stopPenSh[which] != 0;   // was it in prompt|output?
            x = fminf(x, BIG_NEG);
        }
    }
    if (penal) {
        x = (x > 0.0f) ? (x / rp) : (x * rp);
        int c = hlookup(hkey, hcnt, v);
        if (c > 0) x -= fp * (float)c + pp;
    }
    return x * invt;
}

__global__ __launch_bounds__(NT) void sampler_kernel(
    const float* __restrict__ logits,
    const int*   __restrict__ prompt_ids,
    const int*   __restrict__ output_ids,
    const int*   __restrict__ stop_ids,
    const int*   __restrict__ min_tokens,
    const float* __restrict__ presence,
    const float* __restrict__ frequency,
    const float* __restrict__ repetition,
    const float* __restrict__ temperature,
    const int*   __restrict__ top_k,
    const float* __restrict__ top_p,
    const float* __restrict__ noise,
    float*       __restrict__ out,
    int B, int V, int P, int O, int S, int L)
{
    __shared__ unsigned bm[BM_WORDS];          // 16KB: prompt|output|(stops if need)
    __shared__ int   hkey[HASH_SZ];            // output-token count hash (4KB)
    __shared__ int   hcnt[HASH_SZ];
    __shared__ int   scratch[HB];              // 16KB, phase-overlaid:
    int*   hist  = scratch;                    //  phase 1: histogram of thread maxes
    float* candV = reinterpret_cast<float*>(scratch);   // phase 2: candidates
    int*   candI = scratch + CAND_CAP;

    __shared__ float sortedV[64];
    __shared__ int   sortedI[64];
    __shared__ float scoreV[64];
    __shared__ float redf[32];
    __shared__ int   stopPenSh[4];
    __shared__ int   shCand, shNkept;
    __shared__ float shM, shS, shLse, shTheta;

    const int b   = blockIdx.x;
    const int tid = threadIdx.x;

    // ---- init shared ----
    for (int i = tid; i < BM_WORDS; i += NT) bm[i] = 0u;
    for (int i = tid; i < HB;       i += NT) hist[i] = 0;
    for (int i = tid; i < HASH_SZ;  i += NT) { hkey[i] = -1; hcnt[i] = 0; }
    if (tid == 0) shCand = 0;
    __syncthreads();

    // ---- row params ----
    const bool  need = min_tokens[b] > O;
    const float rp = repetition[b], fp = frequency[b], pp = presence[b];
    const float traw = temperature[b];
    const float t = (traw < SAMP_EPS) ? 1.0f : traw;
    const float invt = 1.0f / t;
    const int s0 = (S > 0) ? stop_ids[(size_t)b * S + 0] : -1;
    const int s1 = (S > 1) ? stop_ids[(size_t)b * S + 1] : -1;
    const int s2 = (S > 2) ? stop_ids[(size_t)b * S + 2] : -1;
    const int s3 = (S > 3) ? stop_ids[(size_t)b * S + 3] : -1;

    // ---- build membership bitmap + output counts ----
    for (int i = tid; i < O; i += NT) {
        int tok = output_ids[(size_t)b * O + i];
        atomicOr(&bm[tok >> 5], 1u << (tok & 31));
        unsigned slot = ((unsigned)tok * 2654435761u) & (HASH_SZ - 1);
        while (true) {
            int old = atomicCAS(&hkey[slot], -1, tok);
            if (old == -1 || old == tok) { atomicAdd(&hcnt[slot], 1); break; }
            slot = (slot + 1) & (HASH_SZ - 1);
        }
    }
    for (int i = tid; i < P; i += NT) {
        int tok = prompt_ids[(size_t)b * P + i];
        atomicOr(&bm[tok >> 5], 1u << (tok & 31));
    }
    __syncthreads();

    // ---- fold stop tokens into bitmap (recording prior membership) ----
    if (tid == 0 && need) {
        int ss[4] = {s0, s1, s2, s3};
        int pen[4];
        #pragma unroll
        for (int k = 0; k < 4; k++)
            pen[k] = (ss[k] >= 0) ? (int)((bm[ss[k] >> 5] >> (ss[k] & 31)) & 1u) : 0;
        #pragma unroll
        for (int k = 0; k < 4; k++) {
            stopPenSh[k] = pen[k];
            if (ss[k] >= 0) bm[ss[k] >> 5] |= 1u << (ss[k] & 31);
        }
    }
    __syncthreads();

    const float* lrow = logits + (size_t)b * V;

    // ================= PASS 1: raw max of unmasked (DRAM stream) =================
    float mraw = -CUDART_INF_F;
    for (int base = tid * 8; base < V; base += NT * 8) {
        float4 q0 = *reinterpret_cast<const float4*>(lrow + base);
        float4 q1 = *reinterpret_cast<const float4*>(lrow + base + 4);
        unsigned w = bm[base >> 5];
        const int sh = base & 31;
        float xs[8] = {q0.x, q0.y, q0.z, q0.w, q1.x, q1.y, q1.z, q1.w};
        #pragma unroll
        for (int j = 0; j < 8; j++) {
            float x = ((w >> (sh + j)) & 1u) ? -CUDART_INF_F : xs[j];
            mraw = fmaxf(mraw, x);
        }
    }
    float mx = mraw * invt;                    // -inf stays -inf (invt > 0)

    // ---- fold this thread's special tokens into its max ----
    #pragma unroll
    for (int k = 0; k < WPT; k++) {
        int wi = tid * WPT + k;
        unsigned w = bm[wi];
        int baseTok = wi << 5;
        while (w) {
            int bpos = __ffs(w) - 1; w &= (w - 1);
            int v = baseTok + bpos;
            float x = spec_val(lrow[v], v, need, s0, s1, s2, s3, stopPenSh,
                               rp, fp, pp, invt, hkey, hcnt);
            mx = fmaxf(mx, x);
        }
    }

    // histogram of the 1024 thread-maxes
    atomicAdd(&hist[ordf(mx) >> SHIFT], 1);

    // warp-reduce max
    float wm = mx;
    for (int o = 16; o; o >>= 1) wm = fmaxf(wm, __shfl_xor_sync(0xffffffffu, wm, o));
    if ((tid & 31) == 0) redf[tid >> 5] = wm;
    __syncthreads();                            // hist + redf complete

    if (tid < 32) {
        float v = redf[tid];
        for (int o = 16; o; o >>= 1) v = fmaxf(v, __shfl_xor_sync(0xffffffffu, v, o));
        if (tid == 0) shM = v;
    }
    // ---- threshold: highest bin where cumulative-from-top >= 64 ----
    if (tid >= 32 && tid < 64) {
        const int lt = tid - 32;
        int running = 0;
        for (int base = HB - 1; base >= 0; base -= 32) {
            int bin = base - lt;                // lane 0 = highest bin
            int cnt = (bin >= 0) ? hist[bin] : 0;
            int pref = cnt;                      // inclusive prefix (descending bins)
            for (int o = 1; o < 32; o <<= 1) {
                int nv = __shfl_up_sync(0xffffffffu, pref, o);
                if (lt >= o) pref += nv;
            }
            int tot = __shfl_sync(0xffffffffu, pref, 31);
            if (running + tot >= 64) {
                unsigned msk = __ballot_sync(0xffffffffu, running + pref >= 64);
                int Lm = __ffs(msk) - 1;
                int bstar = base - Lm;
                if (bstar < 0) bstar = 0;
                if (lt == 0) {
                    unsigned tu = (unsigned)bstar << SHIFT;   // bin lower edge
                    float th;
                    if (tu == 0u)               th = -CUDART_INF_F;
                    else if (tu & 0x80000000u)  th = __uint_as_float(tu ^ 0x80000000u);
                    else                        th = __uint_as_float(~tu);
                    shTheta = th;
                }
                break;
            }
            running += tot;
        }
    }
    __syncthreads();

    // ================= PASS 2: exp-sum + candidates (L2-resident) =================
    const float M = shM;
    const float theta = shTheta;
    float s = 0.0f;
    for (int base = tid * 8; base < V; base += NT * 8) {
        float4 q0 = *reinterpret_cast<const float4*>(lrow + base);
        float4 q1 = *reinterpret_cast<const float4*>(lrow + base + 4);
        unsigned w = bm[base >> 5];
        const int sh = base & 31;
        float xs[8] = {q0.x, q0.y, q0.z, q0.w, q1.x, q1.y, q1.z, q1.w};
        #pragma unroll
        for (int j = 0; j < 8; j++) {
            if (!((w >> (sh + j)) & 1u)) {
                float x = xs[j] * invt;
                s += __expf(x - M);
                if (x >= theta) {
                    int p = atomicAdd(&shCand, 1);
                    if (p < CAND_CAP) { candV[p] = x; candI[p] = base + j; }
                }
            }
        }
    }
    // specials: exp-sum + candidate test (fixed per-thread assignment)
    #pragma unroll
    for (int k = 0; k < WPT; k++) {
        int wi = tid * WPT + k;
        unsigned w = bm[wi];
        int baseTok = wi << 5;
        while (w) {
            int bpos = __ffs(w) - 1; w &= (w - 1);
            int v = baseTok + bpos;
            float x = spec_val(lrow[v], v, need, s0, s1, s2, s3, stopPenSh,
                               rp, fp, pp, invt, hkey, hcnt);
            s += __expf(x - M);
            if (x >= theta) {
                int p = atomicAdd(&shCand, 1);
                if (p < CAND_CAP) { candV[p] = x; candI[p] = v; }
            }
        }
    }
    // block sum -> shS (fixed-topology tree: deterministic)
    for (int o = 16; o; o >>= 1) s += __shfl_xor_sync(0xffffffffu, s, o);
    if ((tid & 31) == 0) redf[tid >> 5] = s;
    __syncthreads();
    if (tid < 32) {
        float v = redf[tid];
        for (int o = 16; o; o >>= 1) v += __shfl_xor_sync(0xffffffffu, v, o);
        if (tid == 0) shS = v;
    }
    __syncthreads();

    // ---- exact rank sort of candidates (value desc, index asc; stable) ----
    const int C = min(shCand, CAND_CAP);
    const int Ntop = min(64, C);
    for (int i = tid; i < C; i += NT) {
        float vi = candV[i]; int ii = candI[i];
        int r = 0;
        for (int j = 0; j < C; j++) {
            float vj = candV[j];
            if (vj > vi || (vj == vi && candI[j] < ii)) r++;
        }
        if (r < 64) { sortedV[r] = vi; sortedI[r] = ii; }
    }
    __syncthreads();

    // ---- prefix top-k & top-p (exclusive cumsum, strict <), masked LSE ----
    if (tid == 0) {
        const float Sall = shS;
        int ke = top_k[b]; if (ke < 1) ke = V;
        const float tp = top_p[b];
        float c = 0.0f; int nk = 0;
        for (int i = 0; i < Ntop; i++) {
            if (i < ke && c < tp) { nk = i + 1; c += expf(sortedV[i] - M) / Sall; }
            else break;
        }
        float sum = 0.0f;
        for (int i = 0; i < nk; i++) sum += expf(sortedV[i] - M);
        shLse = M + logf(sum);
        shNkept = nk;
    }
    __syncthreads();
    const int nk = shNkept;
    const float lse = shLse;

    // ---- gumbel scores over kept set (parallel noise gather) ----
    if (tid < nk) {
        int idx = sortedI[tid];
        float u = noise[(size_t)b * V + idx];
        float g = -logf(-logf(u));
        scoreV[tid] = sortedV[tid] * invt + g;
    }
    __syncthreads();
    if (tid == 0) {
        int best;
        if (traw < SAMP_EPS) {
            best = sortedI[0];                       // greedy: ties -> lowest index
        } else {
            best = sortedI[0]; float bs = scoreV[0];
            for (int i = 1; i < nk; i++) {
                float sc = scoreV[i]; int ix = sortedI[i];
                if (sc > bs || (sc == bs && ix < best)) { bs = sc; best = ix; }
            }
        }
        out[b] = (float)best;
    }

    // ---- top-L logprobs + indices ----
    float* lpOut = out + B + (size_t)b * L;
    float* ixOut = out + B + (size_t)B * L + (size_t)b * L;
    if (tid < L) {
        if (tid < nk) {
            lpOut[tid] = sortedV[tid] - lse;
            ixOut[tid] = (float)sortedI[tid];
        } else {
            lpOut[tid] = BIG_NEG;                    // exact: -1e30 - lse == -1e30 in f32
        }
    }
    // fill remaining index slots with the smallest non-kept token ids
    // (lax.top_k tie-break: ascending index among equal BIG_NEG values)
    const int needFill = L - nk;
    if (needFill > 0 && tid < 192) {
        int cid = tid;
        bool inKept = false; int less = 0;
        for (int i = 0; i < nk; i++) {
            int si = sortedI[i];
            inKept |= (si == cid);
            less += (si < cid);
        }
        if (!inKept) {
            int rank = cid - less;                   // rank among non-kept ids
            if (rank < needFill) ixOut[nk + rank] = (float)cid;
        }
    }
}

extern "C" void kernel_launch(void* const* d_in, const int* in_sizes, int n_in,
                              void* d_out, int out_size) {
    const float* logits  = (const float*)d_in[0];
    const int*   prompt  = (const int*)  d_in[1];
    const int*   outtok  = (const int*)  d_in[2];
    const int*   stoptok = (const int*)  d_in[3];
    const int*   mintok  = (const int*)  d_in[4];
    const float* pres    = (const float*)d_in[5];
    const float* freq    = (const float*)d_in[6];
    const float* rep     = (const float*)d_in[7];
    const float* temp    = (const float*)d_in[8];
    const int*   topk    = (const int*)  d_in[9];
    const float* topp    = (const float*)d_in[10];
    const float* noise   = (const float*)d_in[11];

    const int B = in_sizes[4];
    const int V = in_sizes[0] / B;
    const int P = in_sizes[1] / B;
    const int O = in_sizes[2] / B;
    const int S = in_sizes[3] / B;
    const int L = (out_size / B - 1) / 2;   // [sampled(B), logprobs(B,L), indices(B,L)]

    sampler_kernel<<<B, NT>>>(logits, prompt, outtok, stoptok, mintok,
                              pres, freq, rep, temp, topk, topp, noise,
                              (float*)d_out, B, V, P, O, S, L);
}

// round 10
// speedup vs baseline: 2.0679x; 1.0739x over previous
#include <cuda_runtime.h>
#include <cstdint>
#include <math_constants.h>

// Sampler: penalties + temperature + top-k/top-p mask + gumbel sample + top-L logprobs.
// One CTA per row.
//
// R10 vs R9:
//  * exp-sum fused into pass 1 using unshifted exp (x <= ~40 so sum(exp(x)) is
//    f32-safe); global max M eliminated everywhere (epilogue uses exp(v)/S and
//    lse = log(sum_kept exp(v))).
//  * pass 1 also records a per-256-element chunk max (transformed domain).
//  * pass 2 is candidates-only and visits ONLY chunks with chunkMax >= theta
//    (~25% of chunks), distributed via a shared work queue.
// Exactness: theta = (bin lower edge of) 64th-largest thread-max <= x64, same
// order-statistics bound as R9; masked tokens -> -inf in the scans and handled
// exactly in the sparse phases; S accumulation order fixed -> deterministic.

#define NT       1024
#define SHIFT    20
#define HB       4096          // ordered-float bins: ordf(x) >> 20
#define CAND_CAP 2048
#define HASH_SZ  512
#define BM_WORDS 4096          // supports V up to 131072
#define WPT      (BM_WORDS / NT)
#define MAXCHUNK 512           // V/256 <= 512
#define BIG_NEG  (-1e30f)
#define SAMP_EPS 1e-5f

__device__ __forceinline__ unsigned ordf(float x) {
    unsigned u = __float_as_uint(x);
    return (u & 0x80000000u) ? ~u : (u | 0x80000000u);
}

__device__ __forceinline__ int hlookup(const int* hkey, const int* hcnt, int tok) {
    unsigned slot = ((unsigned)tok * 2654435761u) & (HASH_SZ - 1);
    while (true) {
        int k = hkey[slot];
        if (k == tok) return hcnt[slot];
        if (k == -1)  return 0;
        slot = (slot + 1) & (HASH_SZ - 1);
    }
}

// Full reference-order transform for a special (bitmap-marked) token:
// stop-min (if needed) -> repetition (if prompt/output member) -> freq/presence
// (if output member) -> temperature.
__device__ __forceinline__ float spec_val(float x, int v, bool need,
    int s0, int s1, int s2, int s3, const int* stopPenSh,
    float rp, float fp, float pp, float invt,
    const int* hkey, const int* hcnt)
{
    bool penal = true;
    if (need) {
        int which = (v == s0) ? 0 : (v == s1) ? 1 : (v == s2) ? 2 : (v == s3) ? 3 : -1;
        if (which >= 0) {
            penal = stopPenSh[which] != 0;   // was it in prompt|output?
            x = fminf(x, BIG_NEG);
        }
    }
    if (penal) {
        x = (x > 0.0f) ? (x / rp) : (x * rp);
        int c = hlookup(hkey, hcnt, v);
        if (c > 0) x -= fp * (float)c + pp;
    }
    return x * invt;
}

__global__ __launch_bounds__(NT) void sampler_kernel(
    const float* __restrict__ logits,
    const int*   __restrict__ prompt_ids,
    const int*   __restrict__ output_ids,
    const int*   __restrict__ stop_ids,
    const int*   __restrict__ min_tokens,
    const float* __restrict__ presence,
    const float* __restrict__ frequency,
    const float* __restrict__ repetition,
    const float* __restrict__ temperature,
    const int*   __restrict__ top_k,
    const float* __restrict__ top_p,
    const float* __restrict__ noise,
    float*       __restrict__ out,
    int B, int V, int P, int O, int S, int L)
{
    __shared__ unsigned bm[BM_WORDS];          // 16KB: prompt|output|(stops if need)
    __shared__ int   hkey[HASH_SZ];            // output-token count hash (4KB)
    __shared__ int   hcnt[HASH_SZ];
    __shared__ int   scratch[HB];              // 16KB, phase-overlaid:
    int*   hist  = scratch;                    //  phase 1: histogram of thread maxes
    float* candV = reinterpret_cast<float*>(scratch);   // phase 2: candidates
    int*   candI = scratch + CAND_CAP;
    __shared__ float chunkMax[MAXCHUNK];       // 2KB
    __shared__ int   flagged[MAXCHUNK];        // 2KB

    __shared__ float sortedV[64];
    __shared__ int   sortedI[64];
    __shared__ float scoreV[64];
    __shared__ float redf[32];
    __shared__ int   stopPenSh[4];
    __shared__ int   shCand, shNkept, shNFlag, shQHead;
    __shared__ float shS, shLse, shTheta;

    const int b    = blockIdx.x;
    const int tid  = threadIdx.x;
    const int lane = tid & 31;
    const int wid  = tid >> 5;
    const int nChunk = V >> 8;                 // V multiple of 256

    // ---- init shared ----
    for (int i = tid; i < BM_WORDS; i += NT) bm[i] = 0u;
    for (int i = tid; i < HB;       i += NT) hist[i] = 0;
    for (int i = tid; i < HASH_SZ;  i += NT) { hkey[i] = -1; hcnt[i] = 0; }
    if (tid == 0) { shCand = 0; shNFlag = 0; shQHead = 0; }
    __syncthreads();

    // ---- row params ----
    const bool  need = min_tokens[b] > O;
    const float rp = repetition[b], fp = frequency[b], pp = presence[b];
    const float traw = temperature[b];
    const float t = (traw < SAMP_EPS) ? 1.0f : traw;
    const float invt = 1.0f / t;
    const int s0 = (S > 0) ? stop_ids[(size_t)b * S + 0] : -1;
    const int s1 = (S > 1) ? stop_ids[(size_t)b * S + 1] : -1;
    const int s2 = (S > 2) ? stop_ids[(size_t)b * S + 2] : -1;
    const int s3 = (S > 3) ? stop_ids[(size_t)b * S + 3] : -1;

    // ---- build membership bitmap + output counts ----
    for (int i = tid; i < O; i += NT) {
        int tok = output_ids[(size_t)b * O + i];
        atomicOr(&bm[tok >> 5], 1u << (tok & 31));
        unsigned slot = ((unsigned)tok * 2654435761u) & (HASH_SZ - 1);
        while (true) {
            int old = atomicCAS(&hkey[slot], -1, tok);
            if (old == -1 || old == tok) { atomicAdd(&hcnt[slot], 1); break; }
            slot = (slot + 1) & (HASH_SZ - 1);
        }
    }
    for (int i = tid; i < P; i += NT) {
        int tok = prompt_ids[(size_t)b * P + i];
        atomicOr(&bm[tok >> 5], 1u << (tok & 31));
    }
    __syncthreads();

    // ---- fold stop tokens into bitmap (recording prior membership) ----
    if (tid == 0 && need) {
        int ss[4] = {s0, s1, s2, s3};
        int pen[4];
        #pragma unroll
        for (int k = 0; k < 4; k++)
            pen[k] = (ss[k] >= 0) ? (int)((bm[ss[k] >> 5] >> (ss[k] & 31)) & 1u) : 0;
        #pragma unroll
        for (int k = 0; k < 4; k++) {
            stopPenSh[k] = pen[k];
            if (ss[k] >= 0) bm[ss[k] >> 5] |= 1u << (ss[k] & 31);
        }
    }
    __syncthreads();

    const float* lrow = logits + (size_t)b * V;

    // ===== PASS 1 (only full DRAM pass): thread max + exp-sum + chunk maxes =====
    float mx = -CUDART_INF_F;
    float s  = 0.0f;
    for (int it = 0; ; ++it) {
        const int chunk = (it << 5) + wid;          // warp-uniform
        const int cbase = chunk << 8;
        if (cbase >= V) break;
        const int base = cbase + (lane << 3);
        float4 q0 = *reinterpret_cast<const float4*>(lrow + base);
        float4 q1 = *reinterpret_cast<const float4*>(lrow + base + 4);
        unsigned w = bm[base >> 5];
        const int sh = base & 31;
        float xs[8] = {q0.x, q0.y, q0.z, q0.w, q1.x, q1.y, q1.z, q1.w};
        float im = -CUDART_INF_F;
        #pragma unroll
        for (int j = 0; j < 8; j++) {
            float x = ((w >> (sh + j)) & 1u) ? -CUDART_INF_F : xs[j] * invt;
            im = fmaxf(im, x);
            s += __expf(x);                          // exp(-inf) = 0 for masked
        }
        mx = fmaxf(mx, im);
        float cm = im;
        #pragma unroll
        for (int o = 16; o; o >>= 1) cm = fmaxf(cm, __shfl_xor_sync(0xffffffffu, cm, o));
        if (lane == 0) chunkMax[chunk] = cm;
    }

    // ---- specials phase A: fold transformed values into thread max + exp-sum ----
    #pragma unroll
    for (int k = 0; k < WPT; k++) {
        int wi = tid * WPT + k;
        unsigned w = bm[wi];
        int baseTok = wi << 5;
        while (w) {
            int bpos = __ffs(w) - 1; w &= (w - 1);
            int v = baseTok + bpos;
            float x = spec_val(lrow[v], v, need, s0, s1, s2, s3, stopPenSh,
                               rp, fp, pp, invt, hkey, hcnt);
            mx = fmaxf(mx, x);
            s += __expf(x);
        }
    }

    // histogram of the 1024 thread-maxes; warp partial sums
    atomicAdd(&hist[ordf(mx) >> SHIFT], 1);
    float ws = s;
    #pragma unroll
    for (int o = 16; o; o >>= 1) ws += __shfl_xor_sync(0xffffffffu, ws, o);
    if (lane == 0) redf[wid] = ws;
    __syncthreads();                                 // hist + redf + chunkMax complete

    if (wid == 0) {                                  // final exp-sum
        float v = redf[lane];
        #pragma unroll
        for (int o = 16; o; o >>= 1) v += __shfl_xor_sync(0xffffffffu, v, o);
        if (lane == 0) shS = v;
    }
    if (wid == 1) {                                  // theta: cum-from-top >= 64
        int running = 0;
        for (int base = HB - 1; base >= 0; base -= 32) {
            int bin = base - lane;                   // lane 0 = highest bin
            int cnt = (bin >= 0) ? hist[bin] : 0;
            int pref = cnt;
            #pragma unroll
            for (int o = 1; o < 32; o <<= 1) {
                int nv = __shfl_up_sync(0xffffffffu, pref, o);
                if (lane >= o) pref += nv;
            }
            int tot = __shfl_sync(0xffffffffu, pref, 31);
            if (running + tot >= 64) {
                unsigned msk = __ballot_sync(0xffffffffu, running + pref >= 64);
                int Lm = __ffs(msk) - 1;
                int bstar = base - Lm;
                if (bstar < 0) bstar = 0;
                if (lane == 0) {
                    unsigned tu = (unsigned)bstar << SHIFT;   // bin lower edge
                    float th;
                    if (tu == 0u)               th = -CUDART_INF_F;
                    else if (tu & 0x80000000u)  th = __uint_as_float(tu ^ 0x80000000u);
                    else                        th = __uint_as_float(~tu);
                    shTheta = th;
                }
                break;
            }
            running += tot;
        }
    }
    __syncthreads();
    const float theta = shTheta;

    // ---- flag chunks that can contain a candidate ----
    if (tid < nChunk && chunkMax[tid] >= theta) {
        int p = atomicAdd(&shNFlag, 1);
        flagged[p] = tid;
    }
    __syncthreads();
    const int nFlag = shNFlag;

    // ===== PASS 2: candidates only, flagged chunks via work queue (L2) =====
    while (true) {
        int mc;
        if (lane == 0) mc = atomicAdd(&shQHead, 1);
        mc = __shfl_sync(0xffffffffu, mc, 0);
        if (mc >= nFlag) break;
        const int c = flagged[mc];
        const int base = (c << 8) + (lane << 3);
        float4 q0 = *reinterpret_cast<const float4*>(lrow + base);
        float4 q1 = *reinterpret_cast<const float4*>(lrow + base + 4);
        unsigned w = bm[base >> 5];
        const int sh = base & 31;
        float xs[8] = {q0.x, q0.y, q0.z, q0.w, q1.x, q1.y, q1.z, q1.w};
        #pragma unroll
        for (int j = 0; j < 8; j++) {
            if (!((w >> (sh + j)) & 1u)) {
                float x = xs[j] * invt;
                if (x >= theta) {
                    int p = atomicAdd(&shCand, 1);
                    if (p < CAND_CAP) { candV[p] = x; candI[p] = base + j; }
                }
            }
        }
    }
    // specials phase B: candidate test
    #pragma unroll
    for (int k = 0; k < WPT; k++) {
        int wi = tid * WPT + k;
        unsigned w = bm[wi];
        int baseTok = wi << 5;
        while (w) {
            int bpos = __ffs(w) - 1; w &= (w - 1);
            int v = baseTok + bpos;
            float x = spec_val(lrow[v], v, need, s0, s1, s2, s3, stopPenSh,
                               rp, fp, pp, invt, hkey, hcnt);
            if (x >= theta) {
                int p = atomicAdd(&shCand, 1);
                if (p < CAND_CAP) { candV[p] = x; candI[p] = v; }
            }
        }
    }
    __syncthreads();

    // ---- exact rank sort of candidates (value desc, index asc; stable) ----
    const int C = min(shCand, CAND_CAP);
    const int Ntop = min(64, C);
    for (int i = tid; i < C; i += NT) {
        float vi = candV[i]; int ii = candI[i];
        int r = 0;
        for (int j = 0; j < C; j++) {
            float vj = candV[j];
            if (vj > vi || (vj == vi && candI[j] < ii)) r++;
        }
        if (r < 64) { sortedV[r] = vi; sortedI[r] = ii; }
    }
    __syncthreads();

    // ---- prefix top-k & top-p (exclusive cumsum, strict <), masked LSE ----
    if (tid == 0) {
        const float Sall = shS;
        int ke = top_k[b]; if (ke < 1) ke = V;
        const float tp = top_p[b];
        float c = 0.0f; int nk = 0;
        for (int i = 0; i < Ntop; i++) {
            if (i < ke && c < tp) { nk = i + 1; c += expf(sortedV[i]) / Sall; }
            else break;
        }
        float sum = 0.0f;
        for (int i = 0; i < nk; i++) sum += expf(sortedV[i]);
        shLse = logf(sum);
        shNkept = nk;
    }
    __syncthreads();
    const int nk = shNkept;
    const float lse = shLse;

    // ---- gumbel scores over kept set (parallel noise gather) ----
    if (tid < nk) {
        int idx = sortedI[tid];
        float u = noise[(size_t)b * V + idx];
        float g = -logf(-logf(u));
        scoreV[tid] = sortedV[tid] * invt + g;
    }
    __syncthreads();
    if (tid == 0) {
        int best;
        if (traw < SAMP_EPS) {
            best = sortedI[0];                       // greedy: ties -> lowest index
        } else {
            best = sortedI[0]; float bs = scoreV[0];
            for (int i = 1; i < nk; i++) {
                float sc = scoreV[i]; int ix = sortedI[i];
                if (sc > bs || (sc == bs && ix < best)) { bs = sc; best = ix; }
            }
        }
        out[b] = (float)best;
    }

    // ---- top-L logprobs + indices ----
    float* lpOut = out + B + (size_t)b * L;
    float* ixOut = out + B + (size_t)B * L + (size_t)b * L;
    if (tid < L) {
        if (tid < nk) {
            lpOut[tid] = sortedV[tid] - lse;
            ixOut[tid] = (float)sortedI[tid];
        } else {
            lpOut[tid] = BIG_NEG;                    // exact: -1e30 - lse == -1e30 in f32
        }
    }
    // fill remaining index slots with the smallest non-kept token ids
    // (lax.top_k tie-break: ascending index among equal BIG_NEG values)
    const int needFill = L - nk;
    if (needFill > 0 && tid < 192) {
        int cid = tid;
        bool inKept = false; int less = 0;
        for (int i = 0; i < nk; i++) {
            int si = sortedI[i];
            inKept |= (si == cid);
            less += (si < cid);
        }
        if (!inKept) {
            int rank = cid - less;                   // rank among non-kept ids
            if (rank < needFill) ixOut[nk + rank] = (float)cid;
        }
    }
}

extern "C" void kernel_launch(void* const* d_in, const int* in_sizes, int n_in,
                              void* d_out, int out_size) {
    const float* logits  = (const float*)d_in[0];
    const int*   prompt  = (const int*)  d_in[1];
    const int*   outtok  = (const int*)  d_in[2];
    const int*   stoptok = (const int*)  d_in[3];
    const int*   mintok  = (const int*)  d_in[4];
    const float* pres    = (const float*)d_in[5];
    const float* freq    = (const float*)d_in[6];
    const float* rep     = (const float*)d_in[7];
    const float* temp    = (const float*)d_in[8];
    const int*   topk    = (const int*)  d_in[9];
    const float* topp    = (const float*)d_in[10];
    const float* noise   = (const float*)d_in[11];

    const int B = in_sizes[4];
    const int V = in_sizes[0] / B;
    const int P = in_sizes[1] / B;
    const int O = in_sizes[2] / B;
    const int S = in_sizes[3] / B;
    const int L = (out_size / B - 1) / 2;   // [sampled(B), logprobs(B,L), indices(B,L)]

    sampler_kernel<<<B, NT>>>(logits, prompt, outtok, stoptok, mintok,
                              pres, freq, rep, temp, topk, topp, noise,
                              (float*)d_out, B, V, P, O, S, L);
}